// round 8
// baseline (speedup 1.0000x reference)
#include <cuda_runtime.h>
#include <cuda_bf16.h>
#include <cstdint>

#define N_NODES 10000
#define DIN 128
#define H1 8
#define F1 64
#define C1 512            // H1*F1
#define E0 80000
#define NE (2*E0 + N_NODES)   // 170000
#define F2 64
#define NEG_SLOPE 0.2f
#define FULL 0xffffffffu

// ---------------- scratch (static device globals; no allocation) -------------
static __device__ int      g_src[NE];
static __device__ int      g_dst[NE];
static __device__ int      g_cnt[N_NODES];
static __device__ int      g_cursor[N_NODES];
static __device__ int      g_rowptr[N_NODES + 1];
static __device__ int      g_nbr[NE];              // CSR by dst: src indices
static __device__ uint32_t g_B1H[(DIN/2)*C1];      // W1 repacked+split, kpair-major
static __device__ uint32_t g_B1L[(DIN/2)*C1];
static __device__ uint32_t g_B2H[(C1/2)*F2];       // W2 split, kpair-major
static __device__ uint32_t g_B2L[(C1/2)*F2];
static __device__ float    g_proj1[N_NODES*C1];
static __device__ float    g_as1[N_NODES*H1];
static __device__ float    g_an1[N_NODES*H1];
static __device__ float    g_hbuf[N_NODES*C1];     // layer-1 output (post ELU)
static __device__ float    g_proj2[N_NODES*F2];
static __device__ float    g_as2[N_NODES];
static __device__ float    g_an2[N_NODES];

__device__ __forceinline__ void split_pack(float v0, float v1,
                                           uint32_t& hi, uint32_t& lo) {
    __nv_bfloat162 h2 = __floats2bfloat162_rn(v0, v1);
    float r0 = v0 - __low2float(h2);
    float r1 = v1 - __high2float(h2);
    __nv_bfloat162 l2 = __floats2bfloat162_rn(r0, r1);
    hi = *(const uint32_t*)&h2;
    lo = *(const uint32_t*)&l2;
}

// ---------------- prep: edge decode + degree count + W1/W2 split -------------
__global__ void prep_kernel(const int* __restrict__ e32,
                            const float* __restrict__ W1,
                            const float* __restrict__ W2) {
    int i = blockIdx.x * blockDim.x + threadIdx.x;
    if (i < NE) {
        bool is64 = (e32[1] == 0) && (e32[3] == 0) && (e32[5] == 0) && (e32[7] == 0);
        int s, d;
        if (i < NE - N_NODES) {
            int j  = (i < E0) ? i : (i - E0);
            int si = (i < E0) ? j : (E0 + j);
            int di = (i < E0) ? (E0 + j) : j;
            s = is64 ? e32[2*si] : e32[si];
            d = is64 ? e32[2*di] : e32[di];
        } else {
            s = i - (NE - N_NODES); d = s;
        }
        s = min(max(s, 0), N_NODES - 1);
        d = min(max(d, 0), N_NODES - 1);
        g_src[i] = s; g_dst[i] = d;
        atomicAdd(&g_cnt[d], 1);
    }
    // W1 (H,Din,F1) -> kpair-major split [DIN/2][C1]
    if (i < (DIN/2)*C1) {
        int kp = i / C1, c = i % C1;
        int h = c >> 6, f = c & 63;
        float v0 = W1[(h*DIN + 2*kp)*F1 + f];
        float v1 = W1[(h*DIN + 2*kp + 1)*F1 + f];
        split_pack(v0, v1, g_B1H[i], g_B1L[i]);
    }
    // W2 (C1,F2) -> kpair-major split [C1/2][F2]
    if (i < (C1/2)*F2) {
        int kp = i / F2, c = i % F2;
        float v0 = W2[(2*kp)*F2 + c];
        float v1 = W2[(2*kp + 1)*F2 + c];
        split_pack(v0, v1, g_B2H[i], g_B2L[i]);
    }
}

// ---------------- exclusive scan of in-degrees (single block) ----------------
__global__ void scan_kernel() {
    __shared__ int ssum[1024];
    const int t = threadIdx.x;
    const int per = (N_NODES + 1023) / 1024;   // 10
    int base = t * per;
    int loc[16];
    int s = 0;
#pragma unroll
    for (int i = 0; i < per; i++) {
        int idx = base + i;
        int v = (idx < N_NODES) ? g_cnt[idx] : 0;
        loc[i] = v; s += v;
    }
    ssum[t] = s;
    __syncthreads();
    for (int off = 1; off < 1024; off <<= 1) {
        int v = (t >= off) ? ssum[t - off] : 0;
        __syncthreads();
        ssum[t] += v;
        __syncthreads();
    }
    int run = (t > 0) ? ssum[t - 1] : 0;
#pragma unroll
    for (int i = 0; i < per; i++) {
        int idx = base + i;
        if (idx < N_NODES) { g_rowptr[idx] = run; g_cursor[idx] = run; run += loc[i]; }
    }
    if (t == 1023) g_rowptr[N_NODES] = NE;
}

__global__ void fill_csr() {
    int e = blockIdx.x * blockDim.x + threadIdx.x;
    if (e >= NE) return;
    int d = g_dst[e];
    int slot = atomicAdd(&g_cursor[d], 1);   // cursor pre-seeded with rowptr
    g_nbr[slot] = g_src[e];
}

// ---------------- bf16x3 tensor-core MMA (m16n8k16) --------------------------
#define MMA_BF16(D, A0, A1, A2, A3, B0, B1) \
    asm("mma.sync.aligned.m16n8k16.row.col.f32.bf16.bf16.f32 " \
        "{%0,%1,%2,%3}, {%4,%5,%6,%7}, {%8,%9}, {%0,%1,%2,%3};" \
        : "+f"(D[0]), "+f"(D[1]), "+f"(D[2]), "+f"(D[3]) \
        : "r"(A0), "r"(A1), "r"(A2), "r"(A3), "r"(B0), "r"(B1))

// ---------------- GEMM1: 128x64 block tile, fused alpha1 ---------------------
__global__ __launch_bounds__(256) void gemm1_kernel(const float* __restrict__ A,
                                                    const float* __restrict__ a1) {
    __shared__ uint32_t AsH[128][12], AsL[128][12];
    __shared__ uint32_t BsH[64][12],  BsL[64][12];
    __shared__ float sAs[64], sAn[64];
    __shared__ float salS[128][2], salN[128][2];

    const int tid = threadIdx.x;
    const int lane = tid & 31, wid = tid >> 5;
    const int wm = wid >> 1, wn = wid & 1;
    const int g = lane >> 2, tig = lane & 3;
    const int row0 = blockIdx.y * 128;
    const int h = blockIdx.x;
    const int col0 = h * 64;
    const int M = N_NODES;

    if (tid < 64) {
        sAs[tid] = __ldg(&a1[h*2*F1 + tid]);
        sAn[tid] = __ldg(&a1[h*2*F1 + F1 + tid]);
    }

    float acc[2][4][4];
#pragma unroll
    for (int mi = 0; mi < 2; mi++)
#pragma unroll
        for (int ni = 0; ni < 4; ni++)
#pragma unroll
            for (int q = 0; q < 4; q++) acc[mi][ni][q] = 0.f;

    for (int k0 = 0; k0 < DIN; k0 += 16) {
        // A tile: 128 rows x 8 k-pairs, inline split (4/thread)
#pragma unroll
        for (int t = 0; t < 4; t++) {
            int idx = tid + t*256;
            int r = idx >> 3, kk = idx & 7;
            int grow = row0 + r;
            float2 v = (grow < M) ? *(const float2*)&A[(size_t)grow*DIN + k0 + 2*kk]
                                  : make_float2(0.f, 0.f);
            split_pack(v.x, v.y, AsH[r][kk], AsL[r][kk]);
        }
        // B tile: pre-split, 2 coalesced uint32 loads/thread per array
#pragma unroll
        for (int t = 0; t < 2; t++) {
            int idx = tid + t*256;
            int kk = idx >> 6, c = idx & 63;
            size_t gi = (size_t)(k0/2 + kk)*C1 + col0 + c;
            BsH[c][kk] = g_B1H[gi];
            BsL[c][kk] = g_B1L[gi];
        }
        __syncthreads();

        uint32_t bh[4][2], bl[4][2];
#pragma unroll
        for (int ni = 0; ni < 4; ni++) {
            int c = wn*32 + ni*8 + g;
            bh[ni][0] = BsH[c][tig];     bh[ni][1] = BsH[c][tig + 4];
            bl[ni][0] = BsL[c][tig];     bl[ni][1] = BsL[c][tig + 4];
        }
#pragma unroll
        for (int mi = 0; mi < 2; mi++) {
            int r = wm*32 + mi*16 + g;
            uint32_t ah0 = AsH[r][tig],     ah1 = AsH[r + 8][tig];
            uint32_t ah2 = AsH[r][tig + 4], ah3 = AsH[r + 8][tig + 4];
            uint32_t al0 = AsL[r][tig],     al1 = AsL[r + 8][tig];
            uint32_t al2 = AsL[r][tig + 4], al3 = AsL[r + 8][tig + 4];
#pragma unroll
            for (int ni = 0; ni < 4; ni++) {
                MMA_BF16(acc[mi][ni], ah0, ah1, ah2, ah3, bh[ni][0], bh[ni][1]);
                MMA_BF16(acc[mi][ni], ah0, ah1, ah2, ah3, bl[ni][0], bl[ni][1]);
                MMA_BF16(acc[mi][ni], al0, al1, al2, al3, bh[ni][0], bh[ni][1]);
            }
        }
        __syncthreads();
    }

    // epilogue: store proj1 + fused alpha1
#pragma unroll
    for (int mi = 0; mi < 2; mi++) {
        float s0 = 0.f, s8 = 0.f, n0 = 0.f, n8 = 0.f;
        int growA = row0 + wm*32 + mi*16 + g;
        int growB = growA + 8;
#pragma unroll
        for (int ni = 0; ni < 4; ni++) {
            float c0 = acc[mi][ni][0], c1 = acc[mi][ni][1];
            float c2 = acc[mi][ni][2], c3 = acc[mi][ni][3];
            int cl = wn*32 + ni*8 + 2*tig;
            if (growA < M)
                *(float2*)&g_proj1[(size_t)growA*C1 + col0 + cl] = make_float2(c0, c1);
            if (growB < M)
                *(float2*)&g_proj1[(size_t)growB*C1 + col0 + cl] = make_float2(c2, c3);
            float as0 = sAs[cl], as1 = sAs[cl + 1];
            float an0 = sAn[cl], an1 = sAn[cl + 1];
            s0 += c0*as0 + c1*as1;  n0 += c0*an0 + c1*an1;
            s8 += c2*as0 + c3*as1;  n8 += c2*an0 + c3*an1;
        }
#pragma unroll
        for (int o = 1; o <= 2; o <<= 1) {
            s0 += __shfl_xor_sync(FULL, s0, o);
            s8 += __shfl_xor_sync(FULL, s8, o);
            n0 += __shfl_xor_sync(FULL, n0, o);
            n8 += __shfl_xor_sync(FULL, n8, o);
        }
        if (tig == 0) {
            int rl = wm*32 + mi*16 + g;
            salS[rl][wn] = s0;  salN[rl][wn] = n0;
            salS[rl + 8][wn] = s8;  salN[rl + 8][wn] = n8;
        }
    }
    __syncthreads();
    if (tid < 128) {
        int grow = row0 + tid;
        if (grow < M) {
            g_as1[grow*H1 + h] = salS[tid][0] + salS[tid][1];
            g_an1[grow*H1 + h] = salN[tid][0] + salN[tid][1];
        }
    }
}

// ---------------- GEMM2: bf16x3 MMA, 128x64 tile, K=512, fused alpha2 --------
__global__ __launch_bounds__(256) void gemm2_kernel(const float* __restrict__ a2) {
    __shared__ uint32_t AsH[128][12], AsL[128][12];
    __shared__ uint32_t BsH[64][12],  BsL[64][12];
    __shared__ float sAs[64], sAn[64];
    __shared__ float salS[128][2], salN[128][2];

    const int tid = threadIdx.x;
    const int lane = tid & 31, wid = tid >> 5;
    const int wm = wid >> 1, wn = wid & 1;
    const int g = lane >> 2, tig = lane & 3;
    const int row0 = blockIdx.y * 128;
    const int M = N_NODES;
    const float* A = g_hbuf;

    if (tid < 64) {
        sAs[tid] = __ldg(&a2[tid]);
        sAn[tid] = __ldg(&a2[F2 + tid]);
    }

    float acc[2][4][4];
#pragma unroll
    for (int mi = 0; mi < 2; mi++)
#pragma unroll
        for (int ni = 0; ni < 4; ni++)
#pragma unroll
            for (int q = 0; q < 4; q++) acc[mi][ni][q] = 0.f;

    for (int k0 = 0; k0 < C1; k0 += 16) {
#pragma unroll
        for (int t = 0; t < 4; t++) {
            int idx = tid + t*256;
            int r = idx >> 3, kk = idx & 7;
            int grow = row0 + r;
            float2 v = (grow < M) ? *(const float2*)&A[(size_t)grow*C1 + k0 + 2*kk]
                                  : make_float2(0.f, 0.f);
            split_pack(v.x, v.y, AsH[r][kk], AsL[r][kk]);
        }
#pragma unroll
        for (int t = 0; t < 2; t++) {
            int idx = tid + t*256;
            int kk = idx >> 6, c = idx & 63;
            size_t gi = (size_t)(k0/2 + kk)*F2 + c;
            BsH[c][kk] = g_B2H[gi];
            BsL[c][kk] = g_B2L[gi];
        }
        __syncthreads();

        uint32_t bh[4][2], bl[4][2];
#pragma unroll
        for (int ni = 0; ni < 4; ni++) {
            int c = wn*32 + ni*8 + g;
            bh[ni][0] = BsH[c][tig];     bh[ni][1] = BsH[c][tig + 4];
            bl[ni][0] = BsL[c][tig];     bl[ni][1] = BsL[c][tig + 4];
        }
#pragma unroll
        for (int mi = 0; mi < 2; mi++) {
            int r = wm*32 + mi*16 + g;
            uint32_t ah0 = AsH[r][tig],     ah1 = AsH[r + 8][tig];
            uint32_t ah2 = AsH[r][tig + 4], ah3 = AsH[r + 8][tig + 4];
            uint32_t al0 = AsL[r][tig],     al1 = AsL[r + 8][tig];
            uint32_t al2 = AsL[r][tig + 4], al3 = AsL[r + 8][tig + 4];
#pragma unroll
            for (int ni = 0; ni < 4; ni++) {
                MMA_BF16(acc[mi][ni], ah0, ah1, ah2, ah3, bh[ni][0], bh[ni][1]);
                MMA_BF16(acc[mi][ni], ah0, ah1, ah2, ah3, bl[ni][0], bl[ni][1]);
                MMA_BF16(acc[mi][ni], al0, al1, al2, al3, bh[ni][0], bh[ni][1]);
            }
        }
        __syncthreads();
    }

#pragma unroll
    for (int mi = 0; mi < 2; mi++) {
        float s0 = 0.f, s8 = 0.f, n0 = 0.f, n8 = 0.f;
        int growA = row0 + wm*32 + mi*16 + g;
        int growB = growA + 8;
#pragma unroll
        for (int ni = 0; ni < 4; ni++) {
            float c0 = acc[mi][ni][0], c1 = acc[mi][ni][1];
            float c2 = acc[mi][ni][2], c3 = acc[mi][ni][3];
            int cl = wn*32 + ni*8 + 2*tig;
            if (growA < M)
                *(float2*)&g_proj2[(size_t)growA*F2 + cl] = make_float2(c0, c1);
            if (growB < M)
                *(float2*)&g_proj2[(size_t)growB*F2 + cl] = make_float2(c2, c3);
            float as0 = sAs[cl], as1 = sAs[cl + 1];
            float an0 = sAn[cl], an1 = sAn[cl + 1];
            s0 += c0*as0 + c1*as1;  n0 += c0*an0 + c1*an1;
            s8 += c2*as0 + c3*as1;  n8 += c2*an0 + c3*an1;
        }
#pragma unroll
        for (int o = 1; o <= 2; o <<= 1) {
            s0 += __shfl_xor_sync(FULL, s0, o);
            s8 += __shfl_xor_sync(FULL, s8, o);
            n0 += __shfl_xor_sync(FULL, n0, o);
            n8 += __shfl_xor_sync(FULL, n8, o);
        }
        if (tig == 0) {
            int rl = wm*32 + mi*16 + g;
            salS[rl][wn] = s0;  salN[rl][wn] = n0;
            salS[rl + 8][wn] = s8;  salN[rl + 8][wn] = n8;
        }
    }
    __syncthreads();
    if (tid < 128) {
        int grow = row0 + tid;
        if (grow < M) {
            g_as2[grow] = salS[tid][0] + salS[tid][1];
            g_an2[grow] = salN[tid][0] + salN[tid][1];
        }
    }
}

// ---------------- fused gather: softmax + weighted agg + ELU (layer 1) -------
__global__ void gather1() {
    int t = blockIdx.x * blockDim.x + threadIdx.x;
    int w = t >> 5, lane = t & 31;
    if (w >= N_NODES*H1) return;
    int n = w >> 3, h = w & 7;
    int beg = g_rowptr[n], end = g_rowptr[n + 1];
    float as = g_as1[n*H1 + h];

    float mx = -3.0e38f;
    for (int i = beg + lane; i < end; i += 32) {
        float v = as + g_an1[g_nbr[i]*H1 + h];
        v = (v >= 0.f) ? v : NEG_SLOPE*v;
        mx = fmaxf(mx, v);
    }
#pragma unroll
    for (int o = 16; o; o >>= 1) mx = fmaxf(mx, __shfl_xor_sync(FULL, mx, o));

    const int half = lane >> 4;
    const int fl = (lane & 15) * 4;
    const float* projh = g_proj1 + h*F1 + fl;
    float a0 = 0.f, a1v = 0.f, a2v = 0.f, a3 = 0.f, den = 0.f;
    for (int base = beg; base < end; base += 32) {
        int i = base + lane;
        int s = 0; float wgt = 0.f;
        if (i < end) {
            s = g_nbr[i];
            float v = as + g_an1[s*H1 + h];
            v = (v >= 0.f) ? v : NEG_SLOPE*v;
            wgt = __expf(v - mx);
            den += wgt;
        }
        int cnt = min(32, end - base);
        if (cnt == 32) {
#pragma unroll
            for (int j = 0; j < 16; j++) {
                int sl = 2*j + half;
                float ww = __shfl_sync(FULL, wgt, sl);
                int ss = __shfl_sync(FULL, s, sl);
                float4 p = *(const float4*)&projh[(size_t)ss*C1];
                a0 += ww*p.x; a1v += ww*p.y; a2v += ww*p.z; a3 += ww*p.w;
            }
        } else {
            int jmax = (cnt + 1) >> 1;
            for (int j = 0; j < jmax; j++) {
                int sl = 2*j + half;
                float ww = __shfl_sync(FULL, wgt, sl);
                int ss = __shfl_sync(FULL, s, sl);
                float4 p = *(const float4*)&projh[(size_t)ss*C1];
                a0 += ww*p.x; a1v += ww*p.y; a2v += ww*p.z; a3 += ww*p.w;
            }
        }
    }
    a0  += __shfl_xor_sync(FULL, a0, 16);
    a1v += __shfl_xor_sync(FULL, a1v, 16);
    a2v += __shfl_xor_sync(FULL, a2v, 16);
    a3  += __shfl_xor_sync(FULL, a3, 16);
#pragma unroll
    for (int o = 16; o; o >>= 1) den += __shfl_xor_sync(FULL, den, o);
    if (lane < 16) {
        float inv = 1.f / den;
        a0 *= inv; a1v *= inv; a2v *= inv; a3 *= inv;
        a0  = (a0  > 0.f) ? a0  : expm1f(a0);
        a1v = (a1v > 0.f) ? a1v : expm1f(a1v);
        a2v = (a2v > 0.f) ? a2v : expm1f(a2v);
        a3  = (a3  > 0.f) ? a3  : expm1f(a3);
        *(float4*)&g_hbuf[(size_t)n*C1 + h*F1 + fl] = make_float4(a0, a1v, a2v, a3);
    }
}

// ---------------- fused gather layer 2 (H2=1, mean == identity) --------------
__global__ void gather2(float* __restrict__ out) {
    int t = blockIdx.x * blockDim.x + threadIdx.x;
    int w = t >> 5, lane = t & 31;
    if (w >= N_NODES) return;
    int n = w;
    int beg = g_rowptr[n], end = g_rowptr[n + 1];
    float as = g_as2[n];

    float mx = -3.0e38f;
    for (int i = beg + lane; i < end; i += 32) {
        float v = as + g_an2[g_nbr[i]];
        v = (v >= 0.f) ? v : NEG_SLOPE*v;
        mx = fmaxf(mx, v);
    }
#pragma unroll
    for (int o = 16; o; o >>= 1) mx = fmaxf(mx, __shfl_xor_sync(FULL, mx, o));

    const int half = lane >> 4;
    const int fl = (lane & 15) * 4;
    const float* projl = g_proj2 + fl;
    float a0 = 0.f, a1v = 0.f, a2v = 0.f, a3 = 0.f, den = 0.f;
    for (int base = beg; base < end; base += 32) {
        int i = base + lane;
        int s = 0; float wgt = 0.f;
        if (i < end) {
            s = g_nbr[i];
            float v = as + g_an2[s];
            v = (v >= 0.f) ? v : NEG_SLOPE*v;
            wgt = __expf(v - mx);
            den += wgt;
        }
        int cnt = min(32, end - base);
        if (cnt == 32) {
#pragma unroll
            for (int j = 0; j < 16; j++) {
                int sl = 2*j + half;
                float ww = __shfl_sync(FULL, wgt, sl);
                int ss = __shfl_sync(FULL, s, sl);
                float4 p = *(const float4*)&projl[(size_t)ss*F2];
                a0 += ww*p.x; a1v += ww*p.y; a2v += ww*p.z; a3 += ww*p.w;
            }
        } else {
            int jmax = (cnt + 1) >> 1;
            for (int j = 0; j < jmax; j++) {
                int sl = 2*j + half;
                float ww = __shfl_sync(FULL, wgt, sl);
                int ss = __shfl_sync(FULL, s, sl);
                float4 p = *(const float4*)&projl[(size_t)ss*F2];
                a0 += ww*p.x; a1v += ww*p.y; a2v += ww*p.z; a3 += ww*p.w;
            }
        }
    }
    a0  += __shfl_xor_sync(FULL, a0, 16);
    a1v += __shfl_xor_sync(FULL, a1v, 16);
    a2v += __shfl_xor_sync(FULL, a2v, 16);
    a3  += __shfl_xor_sync(FULL, a3, 16);
#pragma unroll
    for (int o = 16; o; o >>= 1) den += __shfl_xor_sync(FULL, den, o);
    if (lane < 16) {
        float inv = 1.f / den;
        *(float4*)&out[(size_t)n*F2 + fl] =
            make_float4(a0*inv, a1v*inv, a2v*inv, a3*inv);
    }
}

// ---------------- launch -------------------------------------------------------
extern "C" void kernel_launch(void* const* d_in, const int* in_sizes, int n_in,
                              void* d_out, int out_size) {
    const float* x     = (const float*)d_in[0];
    const int*   edges = (const int*)d_in[1];
    const float* W1    = (const float*)d_in[2];
    const float* a1    = (const float*)d_in[3];
    const float* W2    = (const float*)d_in[4];
    const float* a2    = (const float*)d_in[5];
    float* out = (float*)d_out;

    void* cnt_ptr = nullptr;
    cudaGetSymbolAddress(&cnt_ptr, g_cnt);
    cudaMemsetAsync(cnt_ptr, 0, N_NODES*sizeof(int));          // launch 1

    prep_kernel<<<(NE + 255)/256, 256>>>(edges, W1, W2);       // launch 2
    scan_kernel<<<1, 1024>>>();                                // launch 3
    fill_csr<<<(NE + 255)/256, 256>>>();                       // launch 4

    // layer 1
    gemm1_kernel<<<dim3(H1, (N_NODES + 127)/128), 256>>>(x, a1);   // launch 5
    gather1<<<(N_NODES*H1*32 + 255)/256, 256>>>();                 // launch 6 -> ncu slot

    // layer 2
    gemm2_kernel<<<dim3(1, (N_NODES + 127)/128), 256>>>(a2);       // launch 7
    gather2<<<(N_NODES*32 + 255)/256, 256>>>(out);                 // launch 8
}